// round 5
// baseline (speedup 1.0000x reference)
#include <cuda_runtime.h>
#include <cuda_bf16.h>

#define N_IN       16
#define FANIN      16
#define N_NODES    512
#define N_OUT      64
#define BATCH      32768
#define OUT_START  (N_NODES - N_OUT)   // node 448

#define THREADS    256
#define GRID       (BATCH / THREADS)   // 128 CTAs, one wave, 2 warps/SMSP

__device__ __forceinline__ float tanh_approx(float x) {
    float y; asm("tanh.approx.f32 %0, %1;" : "=f"(y) : "f"(x)); return y;
}

// Shared memory (float units):
//   [0, 8192)    : resp-folded weights w'[node][tap] = w*resp[src] (32 KB)
//   [8192, 8704) : bias per node (2 KB)
//   [8704, 8768) : resp for the 64 output nodes (256 B)
#define SMEM_W   0
#define SMEM_B   (N_NODES * FANIN)
#define SMEM_R   (SMEM_B + N_NODES)
#define SMEM_F32 (SMEM_R + N_OUT)

__global__ void __launch_bounds__(THREADS, 1)
neat_forward_pipe(const float* __restrict__ x,
                  const float* __restrict__ w,      // [512][16]
                  const float* __restrict__ bias,   // [512]
                  const float* __restrict__ resp,   // [512]
                  float*       __restrict__ out)    // [BATCH][64]
{
    extern __shared__ __align__(16) float sh[];
    const int tid = threadIdx.x;

    // Fold each source's response into the consumer weight:
    //   w'[i][t] = w[i][t] * resp[i + t - 16]  (identity when the source is an input).
    // The register window then carries RAW tanh values; resp is applied only
    // when storing outputs — keeping the recurrence path minimal.
    for (int i = tid; i < N_NODES * FANIN; i += THREADS) {
        const int node = i >> 4, t = i & 15;
        const int g = node + t;                        // global source index
        const float s = (g >= N_IN) ? resp[g - N_IN] : 1.0f;
        sh[SMEM_W + i] = w[i] * s;
    }
    for (int i = tid; i < N_NODES; i += THREADS) sh[SMEM_B + i] = bias[i];
    for (int i = tid; i < N_OUT;   i += THREADS) sh[SMEM_R + i] = resp[OUT_START + i];
    __syncthreads();

    const int b = blockIdx.x * THREADS + tid;          // one batch element per thread

    // Circular register window: v[g & 15] = value at global index g.
    // Node i (j = i & 15) reads v[(j+t)&15], t=0..15 (t=15 newest), writes v[j].
    float v[16];
    {
        const float4* xv = (const float4*)(x + (size_t)b * N_IN);
        #pragma unroll
        for (int q = 0; q < 4; q++) {
            float4 t = xv[q];
            v[4*q+0] = t.x; v[4*q+1] = t.y; v[4*q+2] = t.z; v[4*q+3] = t.w;
        }
    }

    float* outp = out + (size_t)b * N_OUT;
    const float4* wbase = (const float4*)(sh + SMEM_W);

    // Software pipeline: weights/bias for node n are loaded during node n-1's
    // compute (register rotation p* <- n*). LDS latency (29 cyc) is covered by
    // ~26 instruction slots x 2 warps/SMSP of intervening issue.
    float4 p0 = wbase[0], p1 = wbase[1], p2 = wbase[2], p3 = wbase[3];
    float  pb = sh[SMEM_B + 0];

    #pragma unroll 1
    for (int g = 0; g < N_NODES / 16; g++) {
        #pragma unroll
        for (int j = 0; j < 16; j++) {
            const int node = g * 16 + j;
            const int nxt  = (node + 1) & (N_NODES - 1);   // 511 -> 0 (dummy, unused)

            // --- prefetch node+1 (consumed next iteration) ---
            const float4 n0 = wbase[nxt * 4 + 0];
            const float4 n1 = wbase[nxt * 4 + 1];
            const float4 n2 = wbase[nxt * 4 + 2];
            const float4 n3 = wbase[nxt * 4 + 3];
            const float  nb = sh[SMEM_B + nxt];

            // --- compute node with pre-loaded p0..p3, pb ---
            // Taps 0..14 depend only on node-2 and older -> off the serial
            // path; they overlap node-1's tanh. Tap 15 (newest) enters last.
            float a0 = fmaf(v[(j + 0)  & 15], p0.x, pb);
            float a1 =      v[(j + 1)  & 15] * p0.y;
            float a2 =      v[(j + 2)  & 15] * p0.z;
            float a3 =      v[(j + 3)  & 15] * p0.w;
            a0 = fmaf(v[(j + 4)  & 15], p1.x, a0);
            a1 = fmaf(v[(j + 5)  & 15], p1.y, a1);
            a2 = fmaf(v[(j + 6)  & 15], p1.z, a2);
            a3 = fmaf(v[(j + 7)  & 15], p1.w, a3);
            a0 = fmaf(v[(j + 8)  & 15], p2.x, a0);
            a1 = fmaf(v[(j + 9)  & 15], p2.y, a1);
            a2 = fmaf(v[(j + 10) & 15], p2.z, a2);
            a3 = fmaf(v[(j + 11) & 15], p2.w, a3);
            a0 = fmaf(v[(j + 12) & 15], p3.x, a0);
            a1 = fmaf(v[(j + 13) & 15], p3.y, a1);
            a2 = fmaf(v[(j + 14) & 15], p3.z, a2);
            const float partial = (a0 + a1) + (a2 + a3);

            // Serial path per node: ONE fma + tanh.
            const float agg = fmaf(v[(j + 15) & 15], p3.w, partial);
            const float y = tanh_approx(agg);
            v[j] = y;

            if (g >= OUT_START / 16) {
                const int o = node - OUT_START;
                outp[o] = y * sh[SMEM_R + o];          // response applied off-path
            }

            // --- rotate pipeline registers ---
            p0 = n0; p1 = n1; p2 = n2; p3 = n3; pb = nb;
        }
    }
}

extern "C" void kernel_launch(void* const* d_in, const int* in_sizes, int n_in,
                              void* d_out, int out_size) {
    const float* x    = (const float*)d_in[0];   // [BATCH, 16]
    const float* w    = (const float*)d_in[1];   // [512, 16]
    const float* bias = (const float*)d_in[2];   // [512]
    const float* resp = (const float*)d_in[3];   // [512]
    // d_in[4] (src_idx) is the fixed sliding-window topology; baked into indexing.
    float* out = (float*)d_out;                  // [BATCH, 64]

    const int smem_bytes = SMEM_F32 * (int)sizeof(float);   // ~34.3 KB
    neat_forward_pipe<<<GRID, THREADS, smem_bytes>>>(x, w, bias, resp, out);
}